// round 7
// baseline (speedup 1.0000x reference)
#include <cuda_runtime.h>
#include <cstdint>
#include <cstddef>

#define T_STEPS 1024
#define BATCH   256
#define IDIM    128
#define HDIM    128
#define NCLS    18
#define G4      (4*HDIM)              /* 512 */
#define M_TOT   (T_STEPS*BATCH)       /* 262144 */

typedef unsigned long long ull;

/* Scratch (allocation-free rule: __device__ globals). */
__device__ float g_P[(size_t)M_TOT * G4];   /* 512 MB pre-gates */
__device__ float g_h[(size_t)M_TOT * HDIM]; /* 128 MB h_all    */

/* packed f32x2 FMA: d = a*b + d  (two fp32 lanes per instruction) */
__device__ __forceinline__ void ffma2(ull& d, ull a, ull b) {
    asm("fma.rn.f32x2 %0, %1, %2, %0;" : "+l"(d) : "l"(a), "l"(b));
}
__device__ __forceinline__ float hsum2(ull v) {
    float2 f = *(float2*)&v;
    return f.x + f.y;
}
__device__ __forceinline__ ull dup2(float v) {
    ull r; asm("mov.b64 %0, {%1, %1};" : "=l"(r) : "f"(v)); return r;
}
/* accurate fast tanh: (e-1)/(e+1) with e = exp(2x); clamp avoids inf/inf */
__device__ __forceinline__ float fast_tanh(float x) {
    x = fminf(15.f, fmaxf(-15.f, x));
    float e = __expf(2.f * x);
    return (e - 1.f) * __frcp_rn(e + 1.f);
}
__device__ __forceinline__ float fast_sig(float x) {
    return __frcp_rn(1.f + __expf(-x));
}

/* ------------------------------------------------------------------ */
/* Kernel 1: P = X @ W_ih^T + (b_ih + b_hh).  M=262144, N=512, K=128. */
/* Tile M=64 x N=128, full K. 256 thr, 4x8 outputs/thread, f32x2.     */
/* Per k per thread: 3 LDS.128 feed 16 FFMA2 -> FFMA2-floor bound.    */
/* ------------------------------------------------------------------ */
__global__ __launch_bounds__(256) void k_input_gemm(
    const float* __restrict__ X, const float* __restrict__ Wih,
    const float* __restrict__ bih, const float* __restrict__ bhh)
{
    extern __shared__ float sm1[];
    float* Xs = sm1;                 /* [128 k][68]  : m 0..63  */
    float* Ws = sm1 + 128 * 68;      /* [128 k][132] : n 0..127 */

    const int tid = threadIdx.x;
    const int m0 = blockIdx.y * 64;
    const int n0 = blockIdx.x * 128;

    for (int idx = tid; idx < 64 * 128; idx += 256) {
        int r = idx >> 7, k = idx & 127;
        Xs[k * 68 + r] = X[(size_t)(m0 + r) * IDIM + k];
    }
    for (int idx = tid; idx < 128 * 128; idx += 256) {
        int r = idx >> 7, k = idx & 127;
        Ws[k * 132 + r] = Wih[(size_t)(n0 + r) * IDIM + k];
    }
    __syncthreads();

    const int tx = tid & 15, ty = tid >> 4;   /* n base = tx*8, m base = ty*4 */
    ull acc[4][4];
#pragma unroll
    for (int i = 0; i < 4; i++)
#pragma unroll
        for (int jj = 0; jj < 4; jj++) acc[i][jj] = 0ull;

#pragma unroll 4
    for (int k = 0; k < 128; k++) {
        float4 a = *(const float4*)&Xs[k * 68 + ty * 4];
        ulonglong2 b0 = *(const ulonglong2*)&Ws[k * 132 + tx * 8];
        ulonglong2 b1 = *(const ulonglong2*)&Ws[k * 132 + tx * 8 + 4];
        ull ad[4] = {dup2(a.x), dup2(a.y), dup2(a.z), dup2(a.w)};
#pragma unroll
        for (int i = 0; i < 4; i++) {
            ffma2(acc[i][0], ad[i], b0.x);
            ffma2(acc[i][1], ad[i], b0.y);
            ffma2(acc[i][2], ad[i], b1.x);
            ffma2(acc[i][3], ad[i], b1.y);
        }
    }

    float bsv[8];
#pragma unroll
    for (int jj = 0; jj < 8; jj++)
        bsv[jj] = __ldg(&bih[n0 + tx * 8 + jj]) + __ldg(&bhh[n0 + tx * 8 + jj]);

#pragma unroll
    for (int i = 0; i < 4; i++) {
        float2 v0 = *(float2*)&acc[i][0];
        float2 v1 = *(float2*)&acc[i][1];
        float2 v2 = *(float2*)&acc[i][2];
        float2 v3 = *(float2*)&acc[i][3];
        float* dst = &g_P[(size_t)(m0 + ty * 4 + i) * G4 + n0 + tx * 8];
        *(float4*)dst       = make_float4(v0.x + bsv[0], v0.y + bsv[1],
                                          v1.x + bsv[2], v1.y + bsv[3]);
        *(float4*)(dst + 4) = make_float4(v2.x + bsv[4], v2.y + bsv[5],
                                          v3.x + bsv[6], v3.y + bsv[7]);
    }
}

/* ------------------------------------------------------------------ */
/* Kernel 2: recurrence. 128 CTAs x 256 threads; CTA owns 2 batches.  */
/* Thread tid owns gate rows tid and tid+256.                         */
/* W_hh k=0..79 of both rows in REGISTERS (160 regs; no-spill budget),*/
/* k=80..127 in SMEM (stride 52 floats = 13x16B odd -> conflict-free) */
/* ------------------------------------------------------------------ */
__global__ __launch_bounds__(256, 1) void k_lstm(
    const float* __restrict__ h0, const float* __restrict__ c0,
    const float* __restrict__ Whh, float* __restrict__ state_out,
    int write_state)
{
    extern __shared__ float sm2[];
    float* Wsm  = sm2;                  /* [512 rows][52]: k=80..127 (48 floats) */
    float* hbuf = Wsm + 512 * 52;       /* [2 bufs][2 batch][128]                */
    float* gsm  = hbuf + 512;           /* [512 rows][2 batch]                   */

    const int tid = threadIdx.x;
    const int b0  = blockIdx.x * 2;

    /* SMEM tail of W: rows 0..511, k = 80..127 (12 float4 per row) */
    for (int idx = tid; idx < 512 * 12; idx += 256) {
        int row = idx / 12, q = idx % 12;
        *(float4*)&Wsm[row * 52 + 4 * q] =
            *(const float4*)&Whh[(size_t)row * 128 + 80 + 4 * q];
    }

    /* register W: rows tid & tid+256, k-pairs 0..39 (k = 0..79) */
    ull w0[40], w1[40];
    {
        const ulonglong2* wg0 = (const ulonglong2*)(Whh + (size_t)tid * 128);
        const ulonglong2* wg1 = (const ulonglong2*)(Whh + (size_t)(tid + 256) * 128);
#pragma unroll
        for (int q = 0; q < 20; q++) {
            ulonglong2 t0 = wg0[q]; w0[2 * q] = t0.x; w0[2 * q + 1] = t0.y;
            ulonglong2 t1 = wg1[q]; w1[2 * q] = t1.x; w1[2 * q + 1] = t1.y;
        }
    }

    /* init h (smem buf 0) and c (register of epilogue-owner thread) */
    const int eb = tid >> 7, eu = tid & 127;
    float creg = c0[(b0 + eb) * HDIM + eu];
    float hlast = 0.f;
    hbuf[eb * 128 + eu] = h0[(b0 + eb) * HDIM + eu];
    __syncthreads();

    /* P prefetch for t=0 */
    size_t ip = (size_t)b0 * G4;
    float p00 = g_P[ip + tid];
    float p01 = g_P[ip + 512 + tid];
    float p10 = g_P[ip + tid + 256];
    float p11 = g_P[ip + 512 + tid + 256];

    const ulonglong2* ws0 = (const ulonglong2*)(Wsm + tid * 52);
    const ulonglong2* ws1 = (const ulonglong2*)(Wsm + (tid + 256) * 52);

    for (int t = 0; t < T_STEPS; t++) {
        float q00 = p00, q01 = p01, q10 = p10, q11 = p11;
        ip += (size_t)BATCH * G4;
        if (t < T_STEPS - 1) {
            p00 = g_P[ip + tid];
            p01 = g_P[ip + 512 + tid];
            p10 = g_P[ip + tid + 256];
            p11 = g_P[ip + 512 + tid + 256];
        }

        const ulonglong2* hA = (const ulonglong2*)(hbuf + (t & 1) * 256);  /* b0 */
        const ulonglong2* hB = hA + 32;                                    /* b1 */

        ull a00 = 0ull, a01 = 0ull, a10 = 0ull, a11 = 0ull;

        /* k-pairs 0..39 : weights in registers */
#pragma unroll
        for (int q = 0; q < 20; q++) {
            ulonglong2 ha = hA[q];
            ulonglong2 hb = hB[q];
            ffma2(a00, w0[2 * q],     ha.x); ffma2(a00, w0[2 * q + 1], ha.y);
            ffma2(a01, w0[2 * q],     hb.x); ffma2(a01, w0[2 * q + 1], hb.y);
            ffma2(a10, w1[2 * q],     ha.x); ffma2(a10, w1[2 * q + 1], ha.y);
            ffma2(a11, w1[2 * q],     hb.x); ffma2(a11, w1[2 * q + 1], hb.y);
        }
        /* k-pairs 40..63 : weights in SMEM (12 ulonglong2 per row) */
#pragma unroll
        for (int q = 0; q < 12; q++) {
            ulonglong2 ha = hA[20 + q];
            ulonglong2 hb = hB[20 + q];
            ulonglong2 wa = ws0[q];
            ulonglong2 wb = ws1[q];
            ffma2(a00, wa.x, ha.x); ffma2(a00, wa.y, ha.y);
            ffma2(a01, wa.x, hb.x); ffma2(a01, wa.y, hb.y);
            ffma2(a10, wb.x, ha.x); ffma2(a10, wb.y, ha.y);
            ffma2(a11, wb.x, hb.x); ffma2(a11, wb.y, hb.y);
        }

        *(float2*)&gsm[2 * tid]         = make_float2(q00 + hsum2(a00), q01 + hsum2(a01));
        *(float2*)&gsm[2 * (tid + 256)] = make_float2(q10 + hsum2(a10), q11 + hsum2(a11));
        __syncthreads();

        /* epilogue: each of the 256 threads owns one (batch, unit) */
        {
            float gi = gsm[2 * eu + eb];
            float gf = gsm[2 * (128 + eu) + eb];
            float gg = gsm[2 * (256 + eu) + eb];
            float go = gsm[2 * (384 + eu) + eb];
            float iv = fast_sig(gi);
            float fv = fast_sig(gf);
            float gv = fast_tanh(gg);
            float ov = fast_sig(go);
            creg = fv * creg + iv * gv;
            float h = ov * fast_tanh(creg);
            hlast = h;
            hbuf[((t + 1) & 1) * 256 + eb * 128 + eu] = h;
            g_h[((size_t)t * BATCH + b0 + eb) * HDIM + eu] = h;
        }
        __syncthreads();
    }

    if (write_state) {
        state_out[(b0 + eb) * HDIM + eu] = hlast;
        state_out[BATCH * HDIM + (b0 + eb) * HDIM + eu] = creg;
    }
}

/* ------------------------------------------------------------------ */
/* Kernel 3: out = h_all @ fc_W^T + fc_b. One (t,b) row per thread.   */
/* ------------------------------------------------------------------ */
__global__ __launch_bounds__(256) void k_fc(
    const float* __restrict__ fcW, const float* __restrict__ fcb,
    float* __restrict__ out)
{
    __shared__ float Ws[NCLS * HDIM];
    __shared__ float bs[NCLS];
    const int tid = threadIdx.x;
    for (int i = tid; i < NCLS * HDIM; i += 256) Ws[i] = fcW[i];
    if (tid < NCLS) bs[tid] = fcb[tid];
    __syncthreads();

    const size_t m = (size_t)blockIdx.x * 256 + tid;
    const ulonglong2* hv = (const ulonglong2*)(g_h + m * HDIM);

    ull acc[NCLS];
#pragma unroll
    for (int c = 0; c < NCLS; c++) acc[c] = 0ull;

#pragma unroll 2
    for (int q = 0; q < 32; q++) {
        ulonglong2 h = hv[q];
#pragma unroll
        for (int c = 0; c < NCLS; c++) {
            ulonglong2 w = *(const ulonglong2*)&Ws[c * HDIM + 4 * q];
            ffma2(acc[c], w.x, h.x);
            ffma2(acc[c], w.y, h.y);
        }
    }
    float* po = out + m * NCLS;
#pragma unroll
    for (int c = 0; c < NCLS; c++) po[c] = bs[c] + hsum2(acc[c]);
}

/* ------------------------------------------------------------------ */
extern "C" void kernel_launch(void* const* d_in, const int* in_sizes, int n_in,
                              void* d_out, int out_size)
{
    const float* X   = (const float*)d_in[0];
    const float* hid = (const float*)d_in[1];
    const float* cel = (const float*)d_in[2];
    const float* Wih = (const float*)d_in[3];
    const float* Whh = (const float*)d_in[4];
    const float* bih = (const float*)d_in[5];
    const float* bhh = (const float*)d_in[6];
    const float* fcW = (const float*)d_in[7];
    const float* fcb = (const float*)d_in[8];
    float* out = (float*)d_out;

    const int smem1 = (128 * 68 + 128 * 132) * 4;             /* 102400 */
    const int smem2 = (512 * 52 + 512 + 1024) * 4;            /* 112640 */
    cudaFuncSetAttribute(k_input_gemm, cudaFuncAttributeMaxDynamicSharedMemorySize, smem1);
    cudaFuncSetAttribute(k_lstm,       cudaFuncAttributeMaxDynamicSharedMemorySize, smem2);

    k_input_gemm<<<dim3(G4 / 128, M_TOT / 64), 256, smem1>>>(X, Wih, bih, bhh);

    const int main_elems = T_STEPS * BATCH * NCLS;
    int wstate = (out_size >= main_elems + 2 * BATCH * HDIM) ? 1 : 0;
    float* state_out = out + (size_t)main_elems;
    k_lstm<<<BATCH / 2, 256, smem2>>>(hid, cel, Whh, state_out, wstate);

    k_fc<<<M_TOT / 256, 256>>>(fcW, fcb, out);
}

// round 8
// speedup vs baseline: 1.0247x; 1.0247x over previous
#include <cuda_runtime.h>
#include <cstdint>
#include <cstddef>

#define T_STEPS 1024
#define BATCH   256
#define IDIM    128
#define HDIM    128
#define NCLS    18
#define G4      (4*HDIM)              /* 512 */
#define M_TOT   (T_STEPS*BATCH)       /* 262144 */

typedef unsigned long long ull;

/* Scratch (allocation-free rule: __device__ globals). */
__device__ float g_P[(size_t)M_TOT * G4];   /* 512 MB pre-gates */
__device__ float g_h[(size_t)M_TOT * HDIM]; /* 128 MB h_all    */

/* packed f32x2 FMA: d = a*b + d  (two fp32 lanes per instruction) */
__device__ __forceinline__ void ffma2(ull& d, ull a, ull b) {
    asm("fma.rn.f32x2 %0, %1, %2, %0;" : "+l"(d) : "l"(a), "l"(b));
}
__device__ __forceinline__ float hsum2(ull v) {
    float2 f = *(float2*)&v;
    return f.x + f.y;
}
/* accurate fast tanh: (e-1)/(e+1) with e = exp(2x); clamp avoids inf/inf */
__device__ __forceinline__ float fast_tanh(float x) {
    x = fminf(15.f, fmaxf(-15.f, x));
    float e = __expf(2.f * x);
    return (e - 1.f) * __frcp_rn(e + 1.f);
}
__device__ __forceinline__ float fast_sig(float x) {
    return __frcp_rn(1.f + __expf(-x));
}

/* ------------------------------------------------------------------ */
/* Kernel 1: P = X @ W_ih^T + (b_ih + b_hh).  M=262144, N=512, K=128. */
/* 64x64 tile, K split in 2 stages of 64 (smem 51.2KB -> 4 CTAs/SM).  */
/* X stored DUPLICATED in smem: one LDS.128 = two ready f32x2 A-ops.  */
/* Inner loop: 3 LDS.128 + 8 FFMA2 per k, zero MOVs.                  */
/* ------------------------------------------------------------------ */
__global__ __launch_bounds__(256) void k_input_gemm(
    const float* __restrict__ X, const float* __restrict__ Wih,
    const float* __restrict__ bih, const float* __restrict__ bhh)
{
    extern __shared__ float sm1[];
    float* Xd = sm1;                 /* [64 k][132] : m duplicated (128 fl) */
    float* Ws = sm1 + 64 * 132;      /* [64 k][68]  : n 0..63               */

    const int tid = threadIdx.x;
    const int m0 = blockIdx.y * 64;
    const int n0 = blockIdx.x * 64;
    const int tx = tid & 15, ty = tid >> 4;   /* n base = tx*4, m base = ty*4 */

    ull acc[4][2];
#pragma unroll
    for (int i = 0; i < 4; i++) { acc[i][0] = 0ull; acc[i][1] = 0ull; }

#pragma unroll
    for (int ks = 0; ks < 128; ks += 64) {
        /* stage load: X duplicated, W k-major */
        for (int idx = tid; idx < 64 * 64; idx += 256) {
            int r = idx >> 6, k = idx & 63;
            float v = X[(size_t)(m0 + r) * IDIM + ks + k];
            *(float2*)&Xd[k * 132 + 2 * r] = make_float2(v, v);
        }
        for (int idx = tid; idx < 64 * 64; idx += 256) {
            int r = idx >> 6, k = idx & 63;
            Ws[k * 68 + r] = Wih[(size_t)(n0 + r) * IDIM + ks + k];
        }
        __syncthreads();

#pragma unroll 8
        for (int k = 0; k < 64; k++) {
            ulonglong2 a01 = *(const ulonglong2*)&Xd[k * 132 + ty * 8];     /* dup m0,m1 */
            ulonglong2 a23 = *(const ulonglong2*)&Xd[k * 132 + ty * 8 + 4]; /* dup m2,m3 */
            ulonglong2 b   = *(const ulonglong2*)&Ws[k * 68 + tx * 4];      /* n pairs   */
            ffma2(acc[0][0], a01.x, b.x); ffma2(acc[0][1], a01.x, b.y);
            ffma2(acc[1][0], a01.y, b.x); ffma2(acc[1][1], a01.y, b.y);
            ffma2(acc[2][0], a23.x, b.x); ffma2(acc[2][1], a23.x, b.y);
            ffma2(acc[3][0], a23.y, b.x); ffma2(acc[3][1], a23.y, b.y);
        }
        __syncthreads();
    }

    float bsv[4];
#pragma unroll
    for (int jj = 0; jj < 4; jj++)
        bsv[jj] = __ldg(&bih[n0 + tx * 4 + jj]) + __ldg(&bhh[n0 + tx * 4 + jj]);

#pragma unroll
    for (int i = 0; i < 4; i++) {
        float2 lo = *(float2*)&acc[i][0];
        float2 hi = *(float2*)&acc[i][1];
        float4 v = make_float4(lo.x + bsv[0], lo.y + bsv[1],
                               hi.x + bsv[2], hi.y + bsv[3]);
        *(float4*)&g_P[(size_t)(m0 + ty * 4 + i) * G4 + n0 + tx * 4] = v;
    }
}

/* ------------------------------------------------------------------ */
/* Kernel 2: recurrence (R5 known-good config). 128 CTAs x 256 thr.   */
/* Thread tid owns gate rows tid and tid+256.                         */
/* W_hh k=0..95 of both rows in REGISTERS (192 regs),                 */
/* k=96..127 in SMEM (stride 36 -> conflict-free LDS.128).            */
/* ------------------------------------------------------------------ */
__global__ __launch_bounds__(256, 1) void k_lstm(
    const float* __restrict__ h0, const float* __restrict__ c0,
    const float* __restrict__ Whh, float* __restrict__ state_out,
    int write_state)
{
    extern __shared__ float sm2[];
    float* Wsm  = sm2;                  /* [512 rows][36]: k=96..127 (32 floats)  */
    float* hbuf = Wsm + 512 * 36;       /* [2 bufs][2 batch][128]                 */
    float* gsm  = hbuf + 512;           /* [512 rows][2 batch]                    */

    const int tid = threadIdx.x;
    const int b0  = blockIdx.x * 2;

    /* SMEM tail of W: rows 0..511, k = 96..127 */
    for (int idx = tid; idx < 512 * 8; idx += 256) {
        int row = idx >> 3, q = idx & 7;
        *(float4*)&Wsm[row * 36 + 4 * q] =
            *(const float4*)&Whh[(size_t)row * 128 + 96 + 4 * q];
    }

    /* register W: rows tid & tid+256, k-pairs 0..47 (k = 0..95) */
    ull w0[48], w1[48];
    {
        const ulonglong2* wg0 = (const ulonglong2*)(Whh + (size_t)tid * 128);
        const ulonglong2* wg1 = (const ulonglong2*)(Whh + (size_t)(tid + 256) * 128);
#pragma unroll
        for (int q = 0; q < 24; q++) {
            ulonglong2 t0 = wg0[q]; w0[2 * q] = t0.x; w0[2 * q + 1] = t0.y;
            ulonglong2 t1 = wg1[q]; w1[2 * q] = t1.x; w1[2 * q + 1] = t1.y;
        }
    }

    /* init h (smem buf 0) and c (register of epilogue-owner thread) */
    const int eb = tid >> 7, eu = tid & 127;
    float creg = c0[(b0 + eb) * HDIM + eu];
    float hlast = 0.f;
    hbuf[eb * 128 + eu] = h0[(b0 + eb) * HDIM + eu];
    __syncthreads();

    /* P prefetch for t=0 */
    size_t ip = (size_t)b0 * G4;
    float p00 = g_P[ip + tid];
    float p01 = g_P[ip + 512 + tid];
    float p10 = g_P[ip + tid + 256];
    float p11 = g_P[ip + 512 + tid + 256];

    const ulonglong2* ws0 = (const ulonglong2*)(Wsm + tid * 36);
    const ulonglong2* ws1 = (const ulonglong2*)(Wsm + (tid + 256) * 36);

    for (int t = 0; t < T_STEPS; t++) {
        float q00 = p00, q01 = p01, q10 = p10, q11 = p11;
        ip += (size_t)BATCH * G4;
        if (t < T_STEPS - 1) {
            p00 = g_P[ip + tid];
            p01 = g_P[ip + 512 + tid];
            p10 = g_P[ip + tid + 256];
            p11 = g_P[ip + 512 + tid + 256];
        }

        const ulonglong2* hA = (const ulonglong2*)(hbuf + (t & 1) * 256);  /* b0 */
        const ulonglong2* hB = hA + 32;                                    /* b1 */

        ull a00 = 0ull, a01 = 0ull, a10 = 0ull, a11 = 0ull;

        /* k-pairs 0..47 : weights in registers */
#pragma unroll
        for (int q = 0; q < 24; q++) {
            ulonglong2 ha = hA[q];
            ulonglong2 hb = hB[q];
            ffma2(a00, w0[2 * q],     ha.x); ffma2(a00, w0[2 * q + 1], ha.y);
            ffma2(a01, w0[2 * q],     hb.x); ffma2(a01, w0[2 * q + 1], hb.y);
            ffma2(a10, w1[2 * q],     ha.x); ffma2(a10, w1[2 * q + 1], ha.y);
            ffma2(a11, w1[2 * q],     hb.x); ffma2(a11, w1[2 * q + 1], hb.y);
        }
        /* k-pairs 48..63 : weights in SMEM */
#pragma unroll
        for (int q = 0; q < 8; q++) {
            ulonglong2 ha = hA[24 + q];
            ulonglong2 hb = hB[24 + q];
            ulonglong2 wa = ws0[q];
            ulonglong2 wb = ws1[q];
            ffma2(a00, wa.x, ha.x); ffma2(a00, wa.y, ha.y);
            ffma2(a01, wa.x, hb.x); ffma2(a01, wa.y, hb.y);
            ffma2(a10, wb.x, ha.x); ffma2(a10, wb.y, ha.y);
            ffma2(a11, wb.x, hb.x); ffma2(a11, wb.y, hb.y);
        }

        *(float2*)&gsm[2 * tid]         = make_float2(q00 + hsum2(a00), q01 + hsum2(a01));
        *(float2*)&gsm[2 * (tid + 256)] = make_float2(q10 + hsum2(a10), q11 + hsum2(a11));
        __syncthreads();

        /* epilogue: each of the 256 threads owns one (batch, unit) */
        {
            float gi = gsm[2 * eu + eb];
            float gf = gsm[2 * (128 + eu) + eb];
            float gg = gsm[2 * (256 + eu) + eb];
            float go = gsm[2 * (384 + eu) + eb];
            float iv = fast_sig(gi);
            float fv = fast_sig(gf);
            float gv = fast_tanh(gg);
            float ov = fast_sig(go);
            creg = fv * creg + iv * gv;
            float h = ov * fast_tanh(creg);
            hlast = h;
            hbuf[((t + 1) & 1) * 256 + eb * 128 + eu] = h;
            g_h[((size_t)t * BATCH + b0 + eb) * HDIM + eu] = h;
        }
        __syncthreads();
    }

    if (write_state) {
        state_out[(b0 + eb) * HDIM + eu] = hlast;
        state_out[BATCH * HDIM + (b0 + eb) * HDIM + eu] = creg;
    }
}

/* ------------------------------------------------------------------ */
/* Kernel 3: out = h_all @ fc_W^T + fc_b. One (t,b) row per thread.   */
/* ------------------------------------------------------------------ */
__global__ __launch_bounds__(256) void k_fc(
    const float* __restrict__ fcW, const float* __restrict__ fcb,
    float* __restrict__ out)
{
    __shared__ float Ws[NCLS * HDIM];
    __shared__ float bs[NCLS];
    const int tid = threadIdx.x;
    for (int i = tid; i < NCLS * HDIM; i += 256) Ws[i] = fcW[i];
    if (tid < NCLS) bs[tid] = fcb[tid];
    __syncthreads();

    const size_t m = (size_t)blockIdx.x * 256 + tid;
    const ulonglong2* hv = (const ulonglong2*)(g_h + m * HDIM);

    ull acc[NCLS];
#pragma unroll
    for (int c = 0; c < NCLS; c++) acc[c] = 0ull;

#pragma unroll 2
    for (int q = 0; q < 32; q++) {
        ulonglong2 h = hv[q];
#pragma unroll
        for (int c = 0; c < NCLS; c++) {
            ulonglong2 w = *(const ulonglong2*)&Ws[c * HDIM + 4 * q];
            ffma2(acc[c], w.x, h.x);
            ffma2(acc[c], w.y, h.y);
        }
    }
    float* po = out + m * NCLS;
#pragma unroll
    for (int c = 0; c < NCLS; c++) po[c] = bs[c] + hsum2(acc[c]);
}

/* ------------------------------------------------------------------ */
extern "C" void kernel_launch(void* const* d_in, const int* in_sizes, int n_in,
                              void* d_out, int out_size)
{
    const float* X   = (const float*)d_in[0];
    const float* hid = (const float*)d_in[1];
    const float* cel = (const float*)d_in[2];
    const float* Wih = (const float*)d_in[3];
    const float* Whh = (const float*)d_in[4];
    const float* bih = (const float*)d_in[5];
    const float* bhh = (const float*)d_in[6];
    const float* fcW = (const float*)d_in[7];
    const float* fcb = (const float*)d_in[8];
    float* out = (float*)d_out;

    const int smem1 = (64 * 132 + 64 * 68) * 4;               /* 51200  */
    const int smem2 = (512 * 36 + 512 + 1024) * 4;            /* 79872  */
    cudaFuncSetAttribute(k_input_gemm, cudaFuncAttributeMaxDynamicSharedMemorySize, smem1);
    cudaFuncSetAttribute(k_lstm,       cudaFuncAttributeMaxDynamicSharedMemorySize, smem2);

    k_input_gemm<<<dim3(G4 / 64, M_TOT / 64), 256, smem1>>>(X, Wih, bih, bhh);

    const int main_elems = T_STEPS * BATCH * NCLS;
    int wstate = (out_size >= main_elems + 2 * BATCH * HDIM) ? 1 : 0;
    float* state_out = out + (size_t)main_elems;
    k_lstm<<<BATCH / 2, 256, smem2>>>(hid, cel, Whh, state_out, wstate);

    k_fc<<<M_TOT / 256, 256>>>(fcW, fcb, out);
}

// round 10
// speedup vs baseline: 1.1380x; 1.1106x over previous
#include <cuda_runtime.h>
#include <cstdint>
#include <cstddef>

#define T_STEPS 1024
#define BATCH   256
#define IDIM    128
#define HDIM    128
#define NCLS    18
#define G4      (4*HDIM)              /* 512 */
#define M_TOT   (T_STEPS*BATCH)       /* 262144 */

typedef unsigned long long ull;

/* Scratch (allocation-free rule: __device__ globals). */
__device__ float g_P[(size_t)M_TOT * G4];   /* 512 MB pre-gates */
__device__ float g_h[(size_t)M_TOT * HDIM]; /* 128 MB h_all    */

/* packed f32x2 FMA helpers (lstm/fc) */
__device__ __forceinline__ void ffma2(ull& d, ull a, ull b) {
    asm("fma.rn.f32x2 %0, %1, %2, %0;" : "+l"(d) : "l"(a), "l"(b));
}
__device__ __forceinline__ float hsum2(ull v) {
    float2 f = *(float2*)&v;
    return f.x + f.y;
}
__device__ __forceinline__ float fast_tanh(float x) {
    x = fminf(15.f, fmaxf(-15.f, x));
    float e = __expf(2.f * x);
    return (e - 1.f) * __frcp_rn(e + 1.f);
}
__device__ __forceinline__ float fast_sig(float x) {
    return __frcp_rn(1.f + __expf(-x));
}

/* legacy tensor-core mma (PTX ISA standard, compiles on compute_103) */
__device__ __forceinline__ void mma_tf32(float4& d, uint4 a, uint2 b) {
    asm volatile(
        "mma.sync.aligned.m16n8k8.row.col.f32.tf32.tf32.f32 "
        "{%0,%1,%2,%3}, {%4,%5,%6,%7}, {%8,%9}, {%0,%1,%2,%3};"
        : "+f"(d.x), "+f"(d.y), "+f"(d.z), "+f"(d.w)
        : "r"(a.x), "r"(a.y), "r"(a.z), "r"(a.w), "r"(b.x), "r"(b.y));
}
__device__ __forceinline__ void tf32_split(float x, uint32_t& h, uint32_t& l) {
    asm("cvt.rna.tf32.f32 %0, %1;" : "=r"(h) : "f"(x));
    float lf = x - __uint_as_float(h);
    asm("cvt.rna.tf32.f32 %0, %1;" : "=r"(l) : "f"(lf));
}

/* ------------------------------------------------------------------ */
/* Kernel 1 (tensor core, legacy mma.sync, 3xTF32):                   */
/* P = X @ W_ih^T + (b_ih+b_hh).  CTA tile 128M x 64N, K staged x32.  */
/* Fragments pre-permuted in SMEM: A-frag = 1 LDS.128, B-frag = LDS.64*/
/* 8 warps as 4(M) x 2(N); warp tile 32M x 32N.                       */
/* ------------------------------------------------------------------ */
#define K1_SMEM_FLOATS 12288   /* Ahi 4096 | Alo 4096 | Bhi 2048 | Blo 2048 */

__global__ __launch_bounds__(256) void k1_mma(
    const float* __restrict__ X, const float* __restrict__ Wih,
    const float* __restrict__ bih, const float* __restrict__ bhh)
{
    extern __shared__ float sm[];
    uint32_t* Ahi = (uint32_t*)sm;
    uint32_t* Alo = (uint32_t*)(sm + 4096);
    uint32_t* Bhi = (uint32_t*)(sm + 8192);
    uint32_t* Blo = (uint32_t*)(sm + 10240);

    const int tid  = threadIdx.x;
    const int lane = tid & 31;
    const int warp = tid >> 5;
    const int mwid = warp & 3;       /* 0..3 -> m-tiles 2*mwid, +1 */
    const int nwid = warp >> 2;      /* 0..1 -> n-tiles 4*nwid..+3 */
    const int m0 = blockIdx.y * 128;
    const int n0 = blockIdx.x * 64;

    float4 acc[2][4];
#pragma unroll
    for (int i = 0; i < 2; i++)
#pragma unroll
        for (int j = 0; j < 4; j++) acc[i][j] = make_float4(0.f, 0.f, 0.f, 0.f);

    for (int ks = 0; ks < 128; ks += 32) {
        /* ---- load + split A (X tile 128m x 32k) into frag layout ---- */
#pragma unroll
        for (int i = 0; i < 4; i++) {
            int v = tid + 256 * i;
            int q = v & 7, m = v >> 3;           /* k = 4q..4q+3 */
            float4 xv = *(const float4*)&X[(size_t)(m0 + m) * IDIM + ks + q * 4];
            int s = q >> 1, khalf = q & 1;
            int r = ((m >> 3) & 1) + 2 * khalf;  /* a-reg index   */
            int base = ((s * 8 + (m >> 4)) * 32) * 4 + r;
            int lt0 = (m & 7) * 4;
            float xs[4] = {xv.x, xv.y, xv.z, xv.w};
#pragma unroll
            for (int j = 0; j < 4; j++) {
                uint32_t hb, lb;
                tf32_split(xs[j], hb, lb);
                Ahi[base + (lt0 + j) * 4] = hb;
                Alo[base + (lt0 + j) * 4] = lb;
            }
        }
        /* ---- load + split B (W tile 64n x 32k) into frag layout ---- */
#pragma unroll
        for (int i = 0; i < 2; i++) {
            int v = tid + 256 * i;
            int q = v & 7, n = v >> 3;
            float4 wv = *(const float4*)&Wih[(size_t)(n0 + n) * IDIM + ks + q * 4];
            int s = q >> 1, r = q & 1;           /* b-reg index */
            int base = ((s * 8 + (n >> 3)) * 32) * 2 + r;
            int lt0 = (n & 7) * 4;
            float xs[4] = {wv.x, wv.y, wv.z, wv.w};
#pragma unroll
            for (int j = 0; j < 4; j++) {
                uint32_t hb, lb;
                tf32_split(xs[j], hb, lb);
                Bhi[base + (lt0 + j) * 2] = hb;
                Blo[base + (lt0 + j) * 2] = lb;
            }
        }
        __syncthreads();

        /* ---- 4 k-steps of m16n8k8, 3-term split ---- */
#pragma unroll
        for (int s = 0; s < 4; s++) {
            uint4 ah0 = *(uint4*)&Ahi[((s * 8 + 2 * mwid)     * 32 + lane) * 4];
            uint4 ah1 = *(uint4*)&Ahi[((s * 8 + 2 * mwid + 1) * 32 + lane) * 4];
            uint4 al0 = *(uint4*)&Alo[((s * 8 + 2 * mwid)     * 32 + lane) * 4];
            uint4 al1 = *(uint4*)&Alo[((s * 8 + 2 * mwid + 1) * 32 + lane) * 4];
#pragma unroll
            for (int nt = 0; nt < 4; nt++) {
                uint2 bh = *(uint2*)&Bhi[((s * 8 + 4 * nwid + nt) * 32 + lane) * 2];
                uint2 bl = *(uint2*)&Blo[((s * 8 + 4 * nwid + nt) * 32 + lane) * 2];
                mma_tf32(acc[0][nt], ah0, bh);
                mma_tf32(acc[0][nt], ah0, bl);
                mma_tf32(acc[0][nt], al0, bh);
                mma_tf32(acc[1][nt], ah1, bh);
                mma_tf32(acc[1][nt], ah1, bl);
                mma_tf32(acc[1][nt], al1, bh);
            }
        }
        __syncthreads();
    }

    /* ---- epilogue: bias + store ---- */
    const int g = lane >> 2, t = lane & 3;
#pragma unroll
    for (int mi = 0; mi < 2; mi++) {
        int mrow = m0 + (2 * mwid + mi) * 16 + g;
#pragma unroll
        for (int nt = 0; nt < 4; nt++) {
            int nc = n0 + (4 * nwid + nt) * 8 + 2 * t;
            float b0 = __ldg(&bih[nc])     + __ldg(&bhh[nc]);
            float b1 = __ldg(&bih[nc + 1]) + __ldg(&bhh[nc + 1]);
            float4 a = acc[mi][nt];
            *(float2*)&g_P[(size_t)mrow * G4 + nc] = make_float2(a.x + b0, a.y + b1);
            *(float2*)&g_P[(size_t)(mrow + 8) * G4 + nc] = make_float2(a.z + b0, a.w + b1);
        }
    }
}

/* ------------------------------------------------------------------ */
/* Kernel 2: recurrence (R5 exact, 2521-validated).                   */
/* ------------------------------------------------------------------ */
__global__ __launch_bounds__(256, 1) void k_lstm(
    const float* __restrict__ h0, const float* __restrict__ c0,
    const float* __restrict__ Whh, float* __restrict__ state_out,
    int write_state)
{
    extern __shared__ float sm2[];
    float* Wsm  = sm2;                  /* [512 rows][36]: k=96..127 */
    float* hbuf = Wsm + 512 * 36;
    float* gsm  = hbuf + 512;

    const int tid = threadIdx.x;
    const int b0  = blockIdx.x * 2;

    for (int idx = tid; idx < 512 * 8; idx += 256) {
        int row = idx >> 3, q = idx & 7;
        *(float4*)&Wsm[row * 36 + 4 * q] =
            *(const float4*)&Whh[(size_t)row * 128 + 96 + 4 * q];
    }

    ull w0[48], w1[48];
    {
        const ulonglong2* wg0 = (const ulonglong2*)(Whh + (size_t)tid * 128);
        const ulonglong2* wg1 = (const ulonglong2*)(Whh + (size_t)(tid + 256) * 128);
#pragma unroll
        for (int q = 0; q < 24; q++) {
            ulonglong2 t0 = wg0[q]; w0[2 * q] = t0.x; w0[2 * q + 1] = t0.y;
            ulonglong2 t1 = wg1[q]; w1[2 * q] = t1.x; w1[2 * q + 1] = t1.y;
        }
    }

    const int eb = tid >> 7, eu = tid & 127;
    float creg = c0[(b0 + eb) * HDIM + eu];
    float hlast = 0.f;
    hbuf[eb * 128 + eu] = h0[(b0 + eb) * HDIM + eu];
    __syncthreads();

    size_t ip = (size_t)b0 * G4;
    float p00 = g_P[ip + tid];
    float p01 = g_P[ip + 512 + tid];
    float p10 = g_P[ip + tid + 256];
    float p11 = g_P[ip + 512 + tid + 256];

    const ulonglong2* ws0 = (const ulonglong2*)(Wsm + tid * 36);
    const ulonglong2* ws1 = (const ulonglong2*)(Wsm + (tid + 256) * 36);

    for (int t = 0; t < T_STEPS; t++) {
        float q00 = p00, q01 = p01, q10 = p10, q11 = p11;
        ip += (size_t)BATCH * G4;
        if (t < T_STEPS - 1) {
            p00 = g_P[ip + tid];
            p01 = g_P[ip + 512 + tid];
            p10 = g_P[ip + tid + 256];
            p11 = g_P[ip + 512 + tid + 256];
        }

        const ulonglong2* hA = (const ulonglong2*)(hbuf + (t & 1) * 256);
        const ulonglong2* hB = hA + 32;

        ull a00 = 0ull, a01 = 0ull, a10 = 0ull, a11 = 0ull;

#pragma unroll
        for (int q = 0; q < 24; q++) {
            ulonglong2 ha = hA[q];
            ulonglong2 hb = hB[q];
            ffma2(a00, w0[2 * q],     ha.x); ffma2(a00, w0[2 * q + 1], ha.y);
            ffma2(a01, w0[2 * q],     hb.x); ffma2(a01, w0[2 * q + 1], hb.y);
            ffma2(a10, w1[2 * q],     ha.x); ffma2(a10, w1[2 * q + 1], ha.y);
            ffma2(a11, w1[2 * q],     hb.x); ffma2(a11, w1[2 * q + 1], hb.y);
        }
#pragma unroll
        for (int q = 0; q < 8; q++) {
            ulonglong2 ha = hA[24 + q];
            ulonglong2 hb = hB[24 + q];
            ulonglong2 wa = ws0[q];
            ulonglong2 wb = ws1[q];
            ffma2(a00, wa.x, ha.x); ffma2(a00, wa.y, ha.y);
            ffma2(a01, wa.x, hb.x); ffma2(a01, wa.y, hb.y);
            ffma2(a10, wb.x, ha.x); ffma2(a10, wb.y, ha.y);
            ffma2(a11, wb.x, hb.x); ffma2(a11, wb.y, hb.y);
        }

        *(float2*)&gsm[2 * tid]         = make_float2(q00 + hsum2(a00), q01 + hsum2(a01));
        *(float2*)&gsm[2 * (tid + 256)] = make_float2(q10 + hsum2(a10), q11 + hsum2(a11));
        __syncthreads();

        {
            float gi = gsm[2 * eu + eb];
            float gf = gsm[2 * (128 + eu) + eb];
            float gg = gsm[2 * (256 + eu) + eb];
            float go = gsm[2 * (384 + eu) + eb];
            float iv = fast_sig(gi);
            float fv = fast_sig(gf);
            float gv = fast_tanh(gg);
            float ov = fast_sig(go);
            creg = fv * creg + iv * gv;
            float h = ov * fast_tanh(creg);
            hlast = h;
            hbuf[((t + 1) & 1) * 256 + eb * 128 + eu] = h;
            g_h[((size_t)t * BATCH + b0 + eb) * HDIM + eu] = h;
        }
        __syncthreads();
    }

    if (write_state) {
        state_out[(b0 + eb) * HDIM + eu] = hlast;
        state_out[BATCH * HDIM + (b0 + eb) * HDIM + eu] = creg;
    }
}

/* ------------------------------------------------------------------ */
/* Kernel 3: out = h_all @ fc_W^T + fc_b.                             */
/* ------------------------------------------------------------------ */
__global__ __launch_bounds__(256) void k_fc(
    const float* __restrict__ fcW, const float* __restrict__ fcb,
    float* __restrict__ out)
{
    __shared__ float Ws[NCLS * HDIM];
    __shared__ float bsh[NCLS];
    const int tid = threadIdx.x;
    for (int i = tid; i < NCLS * HDIM; i += 256) Ws[i] = fcW[i];
    if (tid < NCLS) bsh[tid] = fcb[tid];
    __syncthreads();

    const size_t m = (size_t)blockIdx.x * 256 + tid;
    const ulonglong2* hv = (const ulonglong2*)(g_h + m * HDIM);

    ull acc[NCLS];
#pragma unroll
    for (int c = 0; c < NCLS; c++) acc[c] = 0ull;

#pragma unroll 2
    for (int q = 0; q < 32; q++) {
        ulonglong2 h = hv[q];
#pragma unroll
        for (int c = 0; c < NCLS; c++) {
            ulonglong2 w = *(const ulonglong2*)&Ws[c * HDIM + 4 * q];
            ffma2(acc[c], w.x, h.x);
            ffma2(acc[c], w.y, h.y);
        }
    }
    float* po = out + m * NCLS;
#pragma unroll
    for (int c = 0; c < NCLS; c++) po[c] = bsh[c] + hsum2(acc[c]);
}

/* ------------------------------------------------------------------ */
extern "C" void kernel_launch(void* const* d_in, const int* in_sizes, int n_in,
                              void* d_out, int out_size)
{
    const float* X   = (const float*)d_in[0];
    const float* hid = (const float*)d_in[1];
    const float* cel = (const float*)d_in[2];
    const float* Wih = (const float*)d_in[3];
    const float* Whh = (const float*)d_in[4];
    const float* bih = (const float*)d_in[5];
    const float* bhh = (const float*)d_in[6];
    const float* fcW = (const float*)d_in[7];
    const float* fcb = (const float*)d_in[8];
    float* out = (float*)d_out;

    const int smem1 = K1_SMEM_FLOATS * 4;                     /* 49152 */
    const int smem2 = (512 * 36 + 512 + 1024) * 4;            /* 79872 */
    cudaFuncSetAttribute(k1_mma, cudaFuncAttributeMaxDynamicSharedMemorySize, smem1);
    cudaFuncSetAttribute(k_lstm, cudaFuncAttributeMaxDynamicSharedMemorySize, smem2);

    k1_mma<<<dim3(G4 / 64, M_TOT / 128), 256, smem1>>>(X, Wih, bih, bhh);

    const int main_elems = T_STEPS * BATCH * NCLS;
    int wstate = (out_size >= main_elems + 2 * BATCH * HDIM) ? 1 : 0;
    float* state_out = out + (size_t)main_elems;
    k_lstm<<<BATCH / 2, 256, smem2>>>(hid, cel, Whh, state_out, wstate);

    k_fc<<<M_TOT / 256, 256>>>(fcW, fcb, out);
}

// round 13
// speedup vs baseline: 1.3961x; 1.2267x over previous
#include <cuda_runtime.h>
#include <cstdint>
#include <cstddef>

#define T_STEPS 1024
#define BATCH   256
#define IDIM    128
#define HDIM    128
#define NCLS    18
#define G4      (4*HDIM)              /* 512 */
#define M_TOT   (T_STEPS*BATCH)       /* 262144 */

typedef unsigned long long ull;

/* Scratch (allocation-free rule: __device__ globals). */
__device__ float g_P[(size_t)M_TOT * G4];   /* 512 MB pre-gates */
__device__ float g_h[(size_t)M_TOT * HDIM]; /* 128 MB h_all    */

/* packed f32x2 FMA helpers (lstm/fc) */
__device__ __forceinline__ void ffma2(ull& d, ull a, ull b) {
    asm("fma.rn.f32x2 %0, %1, %2, %0;" : "+l"(d) : "l"(a), "l"(b));
}
__device__ __forceinline__ float hsum2(ull v) {
    float2 f = *(float2*)&v;
    return f.x + f.y;
}
__device__ __forceinline__ float fast_tanh(float x) {
    x = fminf(15.f, fmaxf(-15.f, x));
    float e = __expf(2.f * x);
    return (e - 1.f) * __frcp_rn(e + 1.f);
}
__device__ __forceinline__ float fast_sig(float x) {
    return __frcp_rn(1.f + __expf(-x));
}

/* ---- tensor core (legacy mma.sync + ldmatrix, PTX-standard) ---- */
__device__ __forceinline__ void mma_tf32(float4& d, uint4 a, uint2 b) {
    asm volatile(
        "mma.sync.aligned.m16n8k8.row.col.f32.tf32.tf32.f32 "
        "{%0,%1,%2,%3}, {%4,%5,%6,%7}, {%8,%9}, {%0,%1,%2,%3};"
        : "+f"(d.x), "+f"(d.y), "+f"(d.z), "+f"(d.w)
        : "r"(a.x), "r"(a.y), "r"(a.z), "r"(a.w), "r"(b.x), "r"(b.y));
}
__device__ __forceinline__ void ldm4(uint4& r, uint32_t addr) {
    asm volatile("ldmatrix.sync.aligned.m8n8.x4.shared.b16 {%0,%1,%2,%3}, [%4];"
                 : "=r"(r.x), "=r"(r.y), "=r"(r.z), "=r"(r.w) : "r"(addr));
}
__device__ __forceinline__ uint32_t smem_u32(const void* p) {
    uint32_t a;
    asm("{ .reg .u64 t; cvta.to.shared.u64 t, %1; cvt.u32.u64 %0, t; }"
        : "=r"(a) : "l"(p));
    return a;
}
__device__ __forceinline__ void tf32_split(float x, uint32_t& h, uint32_t& l) {
    asm("cvt.rna.tf32.f32 %0, %1;" : "=r"(h) : "f"(x));
    float lf = x - __uint_as_float(h);
    asm("cvt.rna.tf32.f32 %0, %1;" : "=r"(l) : "f"(lf));
}
__device__ __forceinline__ void split4(float4 v, float4& h, float4& l) {
    uint32_t a, b;
    tf32_split(v.x, a, b); h.x = __uint_as_float(a); l.x = __uint_as_float(b);
    tf32_split(v.y, a, b); h.y = __uint_as_float(a); l.y = __uint_as_float(b);
    tf32_split(v.z, a, b); h.z = __uint_as_float(a); l.z = __uint_as_float(b);
    tf32_split(v.w, a, b); h.w = __uint_as_float(a); l.w = __uint_as_float(b);
}

/* ------------------------------------------------------------------ */
/* Kernel 1: P = X @ W_ih^T + (b_ih+b_hh) via m16n8k8 tf32 3-split.   */
/* CTA 128M x 64N, K double-buffered in 4 stages of 32.               */
/* Buffer (floats): Ahi[128*32] Alo[128*32] Bhi[64*32] Blo[64*32].    */
/* XOR swizzle: granule(16B) g' = g ^ (row&7). STS.128 + ldmatrix.x4. */
/* ------------------------------------------------------------------ */
#define K1_BUF_FLOATS 12288           /* 49152 B per buffer */
#define K1_SMEM (2 * K1_BUF_FLOATS * 4)

__device__ __forceinline__ void k1_ldg(
    const float* __restrict__ X, const float* __restrict__ Wih,
    int m0, int n0, int ks, float4* xa, float4* wb, int pm, int pq)
{
#pragma unroll
    for (int i = 0; i < 4; i++) {
        int m = i * 32 + pm;
        xa[i] = *(const float4*)&X[(size_t)(m0 + m) * IDIM + ks * 32 + pq * 4];
    }
#pragma unroll
    for (int i = 0; i < 2; i++) {
        int n = i * 32 + pm;
        wb[i] = *(const float4*)&Wih[(size_t)(n0 + n) * IDIM + ks * 32 + pq * 4];
    }
}

__device__ __forceinline__ void k1_sts(
    float* buf, const float4* xa, const float4* wb, int pm, int pq)
{
#pragma unroll
    for (int i = 0; i < 4; i++) {
        int m = i * 32 + pm;
        int g = pq ^ (m & 7);
        float4 h, l;
        split4(xa[i], h, l);
        *(float4*)&buf[m * 32 + g * 4] = h;
        *(float4*)&buf[4096 + m * 32 + g * 4] = l;
    }
#pragma unroll
    for (int i = 0; i < 2; i++) {
        int n = i * 32 + pm;
        int g = pq ^ (n & 7);
        float4 h, l;
        split4(wb[i], h, l);
        *(float4*)&buf[8192 + n * 32 + g * 4] = h;
        *(float4*)&buf[10240 + n * 32 + g * 4] = l;
    }
}

__global__ __launch_bounds__(256) void k1_mma(
    const float* __restrict__ X, const float* __restrict__ Wih,
    const float* __restrict__ bih, const float* __restrict__ bhh)
{
    extern __shared__ float sm[];
    const uint32_t base = smem_u32(sm);

    const int tid  = threadIdx.x;
    const int lane = tid & 31;
    const int warp = tid >> 5;
    const int mwid = warp & 3;       /* m-tiles 2mwid, 2mwid+1 (32 rows) */
    const int nwid = warp >> 2;      /* n cols 32*nwid..+31              */
    const int m0 = blockIdx.y * 128;
    const int n0 = blockIdx.x * 64;

    /* producer mapping */
    const int pm = tid >> 3;         /* row 0..31 (+32 per iter) */
    const int pq = tid & 7;          /* 16B granule              */

    /* consumer ldmatrix row precompute (T = tile index 0..3) */
    const int T = lane >> 3, lr = lane & 7;
    const int rowA0 = mwid * 32 + ((T & 1) << 3) + lr;   /* mt0 */
    const int rowA1 = rowA0 + 16;                        /* mt1 */
    const int khA   = T >> 1;
    const int rowB0 = nwid * 32 + ((T >> 1) << 3) + lr;  /* nt pair 0 */
    const int rowB1 = rowB0 + 16;                        /* nt pair 1 */
    const int khB   = T & 1;

    float4 acc[2][4];
#pragma unroll
    for (int i = 0; i < 2; i++)
#pragma unroll
        for (int j = 0; j < 4; j++) acc[i][j] = make_float4(0.f, 0.f, 0.f, 0.f);

    float4 xa[4], wb[2];

    k1_ldg(X, Wih, m0, n0, 0, xa, wb, pm, pq);
    k1_sts(sm, xa, wb, pm, pq);
    __syncthreads();

#pragma unroll
    for (int ks = 0; ks < 4; ks++) {
        if (ks < 3) k1_ldg(X, Wih, m0, n0, ks + 1, xa, wb, pm, pq);

        const uint32_t bu = base + (uint32_t)(ks & 1) * (K1_BUF_FLOATS * 4);
#pragma unroll
        for (int s = 0; s < 4; s++) {
            const int gA = 2 * s + khA;
            uint32_t a0a = bu + rowA0 * 128 + (uint32_t)((gA ^ (rowA0 & 7)) << 4);
            uint32_t a1a = bu + rowA1 * 128 + (uint32_t)((gA ^ (rowA1 & 7)) << 4);
            uint4 ah0, al0, ah1, al1;
            ldm4(ah0, a0a);
            ldm4(al0, a0a + 16384);
            ldm4(ah1, a1a);
            ldm4(al1, a1a + 16384);

            const int gB = 2 * s + khB;
            uint32_t b0a = bu + 32768 + rowB0 * 128 + (uint32_t)((gB ^ (rowB0 & 7)) << 4);
            uint32_t b1a = bu + 32768 + rowB1 * 128 + (uint32_t)((gB ^ (rowB1 & 7)) << 4);
            uint4 bh0, bl0, bh1, bl1;
            ldm4(bh0, b0a);
            ldm4(bl0, b0a + 8192);
            ldm4(bh1, b1a);
            ldm4(bl1, b1a + 8192);

            uint2 bh[4] = { make_uint2(bh0.x, bh0.y), make_uint2(bh0.z, bh0.w),
                            make_uint2(bh1.x, bh1.y), make_uint2(bh1.z, bh1.w) };
            uint2 bl[4] = { make_uint2(bl0.x, bl0.y), make_uint2(bl0.z, bl0.w),
                            make_uint2(bl1.x, bl1.y), make_uint2(bl1.z, bl1.w) };
#pragma unroll
            for (int nt = 0; nt < 4; nt++) {
                mma_tf32(acc[0][nt], ah0, bh[nt]);
                mma_tf32(acc[0][nt], ah0, bl[nt]);
                mma_tf32(acc[0][nt], al0, bh[nt]);
                mma_tf32(acc[1][nt], ah1, bh[nt]);
                mma_tf32(acc[1][nt], ah1, bl[nt]);
                mma_tf32(acc[1][nt], al1, bh[nt]);
            }
        }

        if (ks < 3) {
            k1_sts(sm + ((ks + 1) & 1) * K1_BUF_FLOATS, xa, wb, pm, pq);
            __syncthreads();
        }
    }

    /* ---- epilogue: bias + store (R10-validated layout) ---- */
    const int g = lane >> 2, t = lane & 3;
#pragma unroll
    for (int mi = 0; mi < 2; mi++) {
        int mrow = m0 + (2 * mwid + mi) * 16 + g;
#pragma unroll
        for (int nt = 0; nt < 4; nt++) {
            int nc = n0 + (4 * nwid + nt) * 8 + 2 * t;
            float b0 = __ldg(&bih[nc])     + __ldg(&bhh[nc]);
            float b1 = __ldg(&bih[nc + 1]) + __ldg(&bhh[nc + 1]);
            float4 a = acc[mi][nt];
            *(float2*)&g_P[(size_t)mrow * G4 + nc] = make_float2(a.x + b0, a.y + b1);
            *(float2*)&g_P[(size_t)(mrow + 8) * G4 + nc] = make_float2(a.z + b0, a.w + b1);
        }
    }
}

/* ------------------------------------------------------------------ */
/* Kernel 2: recurrence (R5 exact, 2521-validated).                   */
/* ------------------------------------------------------------------ */
__global__ __launch_bounds__(256, 1) void k_lstm(
    const float* __restrict__ h0, const float* __restrict__ c0,
    const float* __restrict__ Whh, float* __restrict__ state_out,
    int write_state)
{
    extern __shared__ float sm2[];
    float* Wsm  = sm2;                  /* [512 rows][36]: k=96..127 */
    float* hbuf = Wsm + 512 * 36;
    float* gsm  = hbuf + 512;

    const int tid = threadIdx.x;
    const int b0  = blockIdx.x * 2;

    for (int idx = tid; idx < 512 * 8; idx += 256) {
        int row = idx >> 3, q = idx & 7;
        *(float4*)&Wsm[row * 36 + 4 * q] =
            *(const float4*)&Whh[(size_t)row * 128 + 96 + 4 * q];
    }

    ull w0[48], w1[48];
    {
        const ulonglong2* wg0 = (const ulonglong2*)(Whh + (size_t)tid * 128);
        const ulonglong2* wg1 = (const ulonglong2*)(Whh + (size_t)(tid + 256) * 128);
#pragma unroll
        for (int q = 0; q < 24; q++) {
            ulonglong2 t0 = wg0[q]; w0[2 * q] = t0.x; w0[2 * q + 1] = t0.y;
            ulonglong2 t1 = wg1[q]; w1[2 * q] = t1.x; w1[2 * q + 1] = t1.y;
        }
    }

    const int eb = tid >> 7, eu = tid & 127;
    float creg = c0[(b0 + eb) * HDIM + eu];
    float hlast = 0.f;
    hbuf[eb * 128 + eu] = h0[(b0 + eb) * HDIM + eu];
    __syncthreads();

    size_t ip = (size_t)b0 * G4;
    float p00 = g_P[ip + tid];
    float p01 = g_P[ip + 512 + tid];
    float p10 = g_P[ip + tid + 256];
    float p11 = g_P[ip + 512 + tid + 256];

    const ulonglong2* ws0 = (const ulonglong2*)(Wsm + tid * 36);
    const ulonglong2* ws1 = (const ulonglong2*)(Wsm + (tid + 256) * 36);

    for (int t = 0; t < T_STEPS; t++) {
        float q00 = p00, q01 = p01, q10 = p10, q11 = p11;
        ip += (size_t)BATCH * G4;
        if (t < T_STEPS - 1) {
            p00 = g_P[ip + tid];
            p01 = g_P[ip + 512 + tid];
            p10 = g_P[ip + tid + 256];
            p11 = g_P[ip + 512 + tid + 256];
        }

        const ulonglong2* hA = (const ulonglong2*)(hbuf + (t & 1) * 256);
        const ulonglong2* hB = hA + 32;

        ull a00 = 0ull, a01 = 0ull, a10 = 0ull, a11 = 0ull;

#pragma unroll
        for (int q = 0; q < 24; q++) {
            ulonglong2 ha = hA[q];
            ulonglong2 hb = hB[q];
            ffma2(a00, w0[2 * q],     ha.x); ffma2(a00, w0[2 * q + 1], ha.y);
            ffma2(a01, w0[2 * q],     hb.x); ffma2(a01, w0[2 * q + 1], hb.y);
            ffma2(a10, w1[2 * q],     ha.x); ffma2(a10, w1[2 * q + 1], ha.y);
            ffma2(a11, w1[2 * q],     hb.x); ffma2(a11, w1[2 * q + 1], hb.y);
        }
#pragma unroll
        for (int q = 0; q < 8; q++) {
            ulonglong2 ha = hA[24 + q];
            ulonglong2 hb = hB[24 + q];
            ulonglong2 wa = ws0[q];
            ulonglong2 wb = ws1[q];
            ffma2(a00, wa.x, ha.x); ffma2(a00, wa.y, ha.y);
            ffma2(a01, wa.x, hb.x); ffma2(a01, wa.y, hb.y);
            ffma2(a10, wb.x, ha.x); ffma2(a10, wb.y, ha.y);
            ffma2(a11, wb.x, hb.x); ffma2(a11, wb.y, hb.y);
        }

        *(float2*)&gsm[2 * tid]         = make_float2(q00 + hsum2(a00), q01 + hsum2(a01));
        *(float2*)&gsm[2 * (tid + 256)] = make_float2(q10 + hsum2(a10), q11 + hsum2(a11));
        __syncthreads();

        {
            float gi = gsm[2 * eu + eb];
            float gf = gsm[2 * (128 + eu) + eb];
            float gg = gsm[2 * (256 + eu) + eb];
            float go = gsm[2 * (384 + eu) + eb];
            float iv = fast_sig(gi);
            float fv = fast_sig(gf);
            float gv = fast_tanh(gg);
            float ov = fast_sig(go);
            creg = fv * creg + iv * gv;
            float h = ov * fast_tanh(creg);
            hlast = h;
            hbuf[((t + 1) & 1) * 256 + eb * 128 + eu] = h;
            g_h[((size_t)t * BATCH + b0 + eb) * HDIM + eu] = h;
        }
        __syncthreads();
    }

    if (write_state) {
        state_out[(b0 + eb) * HDIM + eu] = hlast;
        state_out[BATCH * HDIM + (b0 + eb) * HDIM + eu] = creg;
    }
}

/* ------------------------------------------------------------------ */
/* Kernel 3: out = h_all @ fc_W^T + fc_b.                             */
/* ------------------------------------------------------------------ */
__global__ __launch_bounds__(256) void k_fc(
    const float* __restrict__ fcW, const float* __restrict__ fcb,
    float* __restrict__ out)
{
    __shared__ float Ws[NCLS * HDIM];
    __shared__ float bsh[NCLS];
    const int tid = threadIdx.x;
    for (int i = tid; i < NCLS * HDIM; i += 256) Ws[i] = fcW[i];
    if (tid < NCLS) bsh[tid] = fcb[tid];
    __syncthreads();

    const size_t m = (size_t)blockIdx.x * 256 + tid;
    const ulonglong2* hv = (const ulonglong2*)(g_h + m * HDIM);

    ull acc[NCLS];
#pragma unroll
    for (int c = 0; c < NCLS; c++) acc[c] = 0ull;

#pragma unroll 2
    for (int q = 0; q < 32; q++) {
        ulonglong2 h = hv[q];
#pragma unroll
        for (int c = 0; c < NCLS; c++) {
            ulonglong2 w = *(const ulonglong2*)&Ws[c * HDIM + 4 * q];
            ffma2(acc[c], w.x, h.x);
            ffma2(acc[c], w.y, h.y);
        }
    }
    float* po = out + m * NCLS;
#pragma unroll
    for (int c = 0; c < NCLS; c++) po[c] = bsh[c] + hsum2(acc[c]);
}

/* ------------------------------------------------------------------ */
extern "C" void kernel_launch(void* const* d_in, const int* in_sizes, int n_in,
                              void* d_out, int out_size)
{
    const float* X   = (const float*)d_in[0];
    const float* hid = (const float*)d_in[1];
    const float* cel = (const float*)d_in[2];
    const float* Wih = (const float*)d_in[3];
    const float* Whh = (const float*)d_in[4];
    const float* bih = (const float*)d_in[5];
    const float* bhh = (const float*)d_in[6];
    const float* fcW = (const float*)d_in[7];
    const float* fcb = (const float*)d_in[8];
    float* out = (float*)d_out;

    const int smem2 = (512 * 36 + 512 + 1024) * 4;            /* 79872 */
    cudaFuncSetAttribute(k1_mma, cudaFuncAttributeMaxDynamicSharedMemorySize, K1_SMEM);
    cudaFuncSetAttribute(k_lstm, cudaFuncAttributeMaxDynamicSharedMemorySize, smem2);

    k1_mma<<<dim3(G4 / 64, M_TOT / 128), 256, K1_SMEM>>>(X, Wih, bih, bhh);

    const int main_elems = T_STEPS * BATCH * NCLS;
    int wstate = (out_size >= main_elems + 2 * BATCH * HDIM) ? 1 : 0;
    float* state_out = out + (size_t)main_elems;
    k_lstm<<<BATCH / 2, 256, smem2>>>(hid, cel, Whh, state_out, wstate);

    k_fc<<<M_TOT / 256, 256>>>(fcW, fcb, out);
}

// round 14
// speedup vs baseline: 1.5661x; 1.1218x over previous
#include <cuda_runtime.h>
#include <cuda_bf16.h>
#include <cstdint>
#include <cstddef>

#define T_STEPS 1024
#define BATCH   256
#define IDIM    128
#define HDIM    128
#define NCLS    18
#define G4      (4*HDIM)              /* 512 */
#define M_TOT   (T_STEPS*BATCH)       /* 262144 */

typedef unsigned long long ull;

/* Scratch (allocation-free rule: __device__ globals). */
__device__ float g_P[(size_t)M_TOT * G4];   /* 512 MB pre-gates */
__device__ float g_h[(size_t)M_TOT * HDIM]; /* 128 MB h_all    */
/* bf16 hi/mid splits of X and W_ih (written by k0) */
__device__ __nv_bfloat16 g_Xh[(size_t)M_TOT * IDIM];
__device__ __nv_bfloat16 g_Xm[(size_t)M_TOT * IDIM];
__device__ __nv_bfloat16 g_Wh[G4 * IDIM];
__device__ __nv_bfloat16 g_Wm[G4 * IDIM];

/* packed f32x2 FMA helpers (lstm/fc) */
__device__ __forceinline__ void ffma2(ull& d, ull a, ull b) {
    asm("fma.rn.f32x2 %0, %1, %2, %0;" : "+l"(d) : "l"(a), "l"(b));
}
__device__ __forceinline__ float hsum2(ull v) {
    float2 f = *(float2*)&v;
    return f.x + f.y;
}
__device__ __forceinline__ float fast_tanh(float x) {
    x = fminf(15.f, fmaxf(-15.f, x));
    float e = __expf(2.f * x);
    return (e - 1.f) * __frcp_rn(e + 1.f);
}
__device__ __forceinline__ float fast_sig(float x) {
    return __frcp_rn(1.f + __expf(-x));
}

/* ---- tensor core helpers (PTX-standard, compile on compute_103) ---- */
__device__ __forceinline__ void mma_bf16(float4& d, uint4 a, uint2 b) {
    asm volatile(
        "mma.sync.aligned.m16n8k16.row.col.f32.bf16.bf16.f32 "
        "{%0,%1,%2,%3}, {%4,%5,%6,%7}, {%8,%9}, {%0,%1,%2,%3};"
        : "+f"(d.x), "+f"(d.y), "+f"(d.z), "+f"(d.w)
        : "r"(a.x), "r"(a.y), "r"(a.z), "r"(a.w), "r"(b.x), "r"(b.y));
}
__device__ __forceinline__ void ldm4(uint4& r, uint32_t addr) {
    asm volatile("ldmatrix.sync.aligned.m8n8.x4.shared.b16 {%0,%1,%2,%3}, [%4];"
                 : "=r"(r.x), "=r"(r.y), "=r"(r.z), "=r"(r.w) : "r"(addr));
}
__device__ __forceinline__ uint32_t smem_u32(const void* p) {
    uint32_t a;
    asm("{ .reg .u64 t; cvta.to.shared.u64 t, %1; cvt.u32.u64 %0, t; }"
        : "=r"(a) : "l"(p));
    return a;
}
__device__ __forceinline__ ull gaddr(const void* p) {
    ull a; asm("cvta.to.global.u64 %0, %1;" : "=l"(a) : "l"(p)); return a;
}
#define CP_ASYNC16(dst, src) \
    asm volatile("cp.async.cg.shared.global [%0], [%1], 16;" :: "r"(dst), "l"(src))
#define CP_COMMIT() asm volatile("cp.async.commit_group;" ::: "memory")
#define CP_WAIT(n)  asm volatile("cp.async.wait_group %0;" :: "n"(n) : "memory")

/* ------------------------------------------------------------------ */
/* Kernel 0: split X, W_ih into bf16 hi/mid (x = hi + mid + O(2^-16)) */
/* ------------------------------------------------------------------ */
#define X_F4 8388608                  /* M_TOT*IDIM/4 */
#define W_F4 16384                    /* G4*IDIM/4    */

__global__ __launch_bounds__(256) void k0_split(
    const float* __restrict__ X, const float* __restrict__ Wih)
{
    size_t i4 = (size_t)blockIdx.x * 256 + threadIdx.x;
    float4 v;
    __nv_bfloat16 *dh, *dm;
    size_t e;
    if (i4 < X_F4) {
        v = ((const float4*)X)[i4];
        e = i4 * 4; dh = g_Xh; dm = g_Xm;
    } else {
        size_t j = i4 - X_F4;
        if (j >= W_F4) return;
        v = ((const float4*)Wih)[j];
        e = j * 4; dh = g_Wh; dm = g_Wm;
    }
    float xs[4] = {v.x, v.y, v.z, v.w};
    __nv_bfloat16 h[4], m[4];
#pragma unroll
    for (int i = 0; i < 4; i++) {
        h[i] = __float2bfloat16_rn(xs[i]);
        float r = xs[i] - __bfloat162float(h[i]);
        m[i] = __float2bfloat16_rn(r);
    }
    __nv_bfloat162 h01, h23, m01, m23;
    h01.x = h[0]; h01.y = h[1]; h23.x = h[2]; h23.y = h[3];
    m01.x = m[0]; m01.y = m[1]; m23.x = m[2]; m23.y = m[3];
    *(uint2*)(dh + e) = make_uint2(*(uint32_t*)&h01, *(uint32_t*)&h23);
    *(uint2*)(dm + e) = make_uint2(*(uint32_t*)&m01, *(uint32_t*)&m23);
}

/* ------------------------------------------------------------------ */
/* Kernel 1: P = X @ W_ih^T + (b_ih+b_hh), bf16 4-term m16n8k16.      */
/* CTA 128M x 64N; K 4 stages of 32, cp.async double-buffered.        */
/* SMEM stage (bytes): Ah[128*80] Am[128*80] Bh[64*80] Bm[64*80]      */
/* rows padded to 80B -> ldmatrix conflict-free (5r+g distinct mod 8) */
/* ------------------------------------------------------------------ */
#define K1_A_LVL   10240              /* 128*80 */
#define K1_B_BASE  20480
#define K1_B_LVL   5120               /* 64*80  */
#define K1_STAGE   30720
#define K1_SMEM    (2 * K1_STAGE)     /* 61440  */

__device__ __forceinline__ void k1_issue(
    uint32_t sbase, int m0, int n0, int ks, int tid)
{
    /* A: 1024 granules (2 lvl x 128 rows x 4), B: 512 (2 x 64 x 4) */
#pragma unroll
    for (int i = 0; i < 4; i++) {
        int v = tid + 256 * i;
        int lvl = v >> 9, rem = v & 511;
        int r = rem >> 2, g = rem & 3;
        const __nv_bfloat16* src = (lvl ? g_Xm : g_Xh)
            + ((size_t)(m0 + r) * IDIM + ks * 32 + g * 8);
        CP_ASYNC16(sbase + lvl * K1_A_LVL + r * 80 + g * 16, gaddr(src));
    }
#pragma unroll
    for (int i = 0; i < 2; i++) {
        int v = tid + 256 * i;
        int lvl = v >> 8, rem = v & 255;
        int r = rem >> 2, g = rem & 3;
        const __nv_bfloat16* src = (lvl ? g_Wm : g_Wh)
            + ((size_t)(n0 + r) * IDIM + ks * 32 + g * 8);
        CP_ASYNC16(sbase + K1_B_BASE + lvl * K1_B_LVL + r * 80 + g * 16, gaddr(src));
    }
    CP_COMMIT();
}

__global__ __launch_bounds__(256) void k1_mma(
    const float* __restrict__ bih, const float* __restrict__ bhh)
{
    extern __shared__ char sm[];
    const uint32_t base = smem_u32(sm);

    const int tid  = threadIdx.x;
    const int lane = tid & 31;
    const int warp = tid >> 5;
    const int mwid = warp & 3;       /* rows mwid*32..+31 */
    const int nwid = warp >> 2;      /* cols nwid*32..+31 */
    const int m0 = blockIdx.y * 128;
    const int n0 = blockIdx.x * 64;

    /* ldmatrix lane addressing (T = lane>>3 selects 8x8 tile) */
    const int lr = lane & 7, T = lane >> 3;
    /* A tiles: T0=(mlo,klo) T1=(mhi,klo) T2=(mlo,khi) T3=(mhi,khi) */
    const uint32_t aOff = (uint32_t)((mwid * 32 + (T & 1) * 8 + lr) * 80 + (T >> 1) * 16);
    /* B tiles: T0=(ntA,klo) T1=(ntA,khi) T2=(ntB,klo) T3=(ntB,khi) */
    const uint32_t bOff = (uint32_t)(K1_B_BASE + (nwid * 32 + (T >> 1) * 8 + lr) * 80 + (T & 1) * 16);

    float4 acc[2][4];
#pragma unroll
    for (int i = 0; i < 2; i++)
#pragma unroll
        for (int j = 0; j < 4; j++) acc[i][j] = make_float4(0.f, 0.f, 0.f, 0.f);

    k1_issue(base, m0, n0, 0, tid);
    k1_issue(base + K1_STAGE, m0, n0, 1, tid);

#pragma unroll
    for (int ks = 0; ks < 4; ks++) {
        if (ks == 3) { CP_WAIT(0); } else { CP_WAIT(1); }
        __syncthreads();

        const uint32_t bu = base + (uint32_t)(ks & 1) * K1_STAGE;
#pragma unroll
        for (int kc = 0; kc < 2; kc++) {
            uint4 Ah[2], Am[2];
#pragma unroll
            for (int mt = 0; mt < 2; mt++) {
                uint32_t a = bu + aOff + (uint32_t)(mt * 1280 + kc * 32);
                ldm4(Ah[mt], a);
                ldm4(Am[mt], a + K1_A_LVL);
            }
            uint4 Bh0, Bh1, Bm0, Bm1;
            {
                uint32_t b0 = bu + bOff + (uint32_t)(kc * 32);
                uint32_t b1 = b0 + 1280;
                ldm4(Bh0, b0);
                ldm4(Bh1, b1);
                ldm4(Bm0, b0 + K1_B_LVL);
                ldm4(Bm1, b1 + K1_B_LVL);
            }
            uint2 bh[4] = { make_uint2(Bh0.x, Bh0.y), make_uint2(Bh0.z, Bh0.w),
                            make_uint2(Bh1.x, Bh1.y), make_uint2(Bh1.z, Bh1.w) };
            uint2 bm[4] = { make_uint2(Bm0.x, Bm0.y), make_uint2(Bm0.z, Bm0.w),
                            make_uint2(Bm1.x, Bm1.y), make_uint2(Bm1.z, Bm1.w) };
#pragma unroll
            for (int mt = 0; mt < 2; mt++)
#pragma unroll
                for (int nt = 0; nt < 4; nt++) {
                    mma_bf16(acc[mt][nt], Ah[mt], bh[nt]);
                    mma_bf16(acc[mt][nt], Ah[mt], bm[nt]);
                    mma_bf16(acc[mt][nt], Am[mt], bh[nt]);
                    mma_bf16(acc[mt][nt], Am[mt], bm[nt]);
                }
        }

        if (ks < 2) {
            __syncthreads();   /* all reads of buffer (ks&1) done */
            k1_issue(base + (uint32_t)(ks & 1) * K1_STAGE, m0, n0, ks + 2, tid);
        }
    }

    /* ---- epilogue: bias + store (R13-validated c-frag layout) ---- */
    const int g = lane >> 2, t = lane & 3;
#pragma unroll
    for (int mi = 0; mi < 2; mi++) {
        int mrow = m0 + (2 * mwid + mi) * 16 + g;
#pragma unroll
        for (int nt = 0; nt < 4; nt++) {
            int nc = n0 + (4 * nwid + nt) * 8 + 2 * t;
            float b0 = __ldg(&bih[nc])     + __ldg(&bhh[nc]);
            float b1 = __ldg(&bih[nc + 1]) + __ldg(&bhh[nc + 1]);
            float4 a = acc[mi][nt];
            *(float2*)&g_P[(size_t)mrow * G4 + nc] = make_float2(a.x + b0, a.y + b1);
            *(float2*)&g_P[(size_t)(mrow + 8) * G4 + nc] = make_float2(a.z + b0, a.w + b1);
        }
    }
}

/* ------------------------------------------------------------------ */
/* Kernel 2: recurrence (R5 exact, 2521-validated).                   */
/* ------------------------------------------------------------------ */
__global__ __launch_bounds__(256, 1) void k_lstm(
    const float* __restrict__ h0, const float* __restrict__ c0,
    const float* __restrict__ Whh, float* __restrict__ state_out,
    int write_state)
{
    extern __shared__ float sm2[];
    float* Wsm  = sm2;                  /* [512 rows][36]: k=96..127 */
    float* hbuf = Wsm + 512 * 36;
    float* gsm  = hbuf + 512;

    const int tid = threadIdx.x;
    const int b0  = blockIdx.x * 2;

    for (int idx = tid; idx < 512 * 8; idx += 256) {
        int row = idx >> 3, q = idx & 7;
        *(float4*)&Wsm[row * 36 + 4 * q] =
            *(const float4*)&Whh[(size_t)row * 128 + 96 + 4 * q];
    }

    ull w0[48], w1[48];
    {
        const ulonglong2* wg0 = (const ulonglong2*)(Whh + (size_t)tid * 128);
        const ulonglong2* wg1 = (const ulonglong2*)(Whh + (size_t)(tid + 256) * 128);
#pragma unroll
        for (int q = 0; q < 24; q++) {
            ulonglong2 t0 = wg0[q]; w0[2 * q] = t0.x; w0[2 * q + 1] = t0.y;
            ulonglong2 t1 = wg1[q]; w1[2 * q] = t1.x; w1[2 * q + 1] = t1.y;
        }
    }

    const int eb = tid >> 7, eu = tid & 127;
    float creg = c0[(b0 + eb) * HDIM + eu];
    float hlast = 0.f;
    hbuf[eb * 128 + eu] = h0[(b0 + eb) * HDIM + eu];
    __syncthreads();

    size_t ip = (size_t)b0 * G4;
    float p00 = g_P[ip + tid];
    float p01 = g_P[ip + 512 + tid];
    float p10 = g_P[ip + tid + 256];
    float p11 = g_P[ip + 512 + tid + 256];

    const ulonglong2* ws0 = (const ulonglong2*)(Wsm + tid * 36);
    const ulonglong2* ws1 = (const ulonglong2*)(Wsm + (tid + 256) * 36);

    for (int t = 0; t < T_STEPS; t++) {
        float q00 = p00, q01 = p01, q10 = p10, q11 = p11;
        ip += (size_t)BATCH * G4;
        if (t < T_STEPS - 1) {
            p00 = g_P[ip + tid];
            p01 = g_P[ip + 512 + tid];
            p10 = g_P[ip + tid + 256];
            p11 = g_P[ip + 512 + tid + 256];
        }

        const ulonglong2* hA = (const ulonglong2*)(hbuf + (t & 1) * 256);
        const ulonglong2* hB = hA + 32;

        ull a00 = 0ull, a01 = 0ull, a10 = 0ull, a11 = 0ull;

#pragma unroll
        for (int q = 0; q < 24; q++) {
            ulonglong2 ha = hA[q];
            ulonglong2 hb = hB[q];
            ffma2(a00, w0[2 * q],     ha.x); ffma2(a00, w0[2 * q + 1], ha.y);
            ffma2(a01, w0[2 * q],     hb.x); ffma2(a01, w0[2 * q + 1], hb.y);
            ffma2(a10, w1[2 * q],     ha.x); ffma2(a10, w1[2 * q + 1], ha.y);
            ffma2(a11, w1[2 * q],     hb.x); ffma2(a11, w1[2 * q + 1], hb.y);
        }
#pragma unroll
        for (int q = 0; q < 8; q++) {
            ulonglong2 ha = hA[24 + q];
            ulonglong2 hb = hB[24 + q];
            ulonglong2 wa = ws0[q];
            ulonglong2 wb = ws1[q];
            ffma2(a00, wa.x, ha.x); ffma2(a00, wa.y, ha.y);
            ffma2(a01, wa.x, hb.x); ffma2(a01, wa.y, hb.y);
            ffma2(a10, wb.x, ha.x); ffma2(a10, wb.y, ha.y);
            ffma2(a11, wb.x, hb.x); ffma2(a11, wb.y, hb.y);
        }

        *(float2*)&gsm[2 * tid]         = make_float2(q00 + hsum2(a00), q01 + hsum2(a01));
        *(float2*)&gsm[2 * (tid + 256)] = make_float2(q10 + hsum2(a10), q11 + hsum2(a11));
        __syncthreads();

        {
            float gi = gsm[2 * eu + eb];
            float gf = gsm[2 * (128 + eu) + eb];
            float gg = gsm[2 * (256 + eu) + eb];
            float go = gsm[2 * (384 + eu) + eb];
            float iv = fast_sig(gi);
            float fv = fast_sig(gf);
            float gv = fast_tanh(gg);
            float ov = fast_sig(go);
            creg = fv * creg + iv * gv;
            float h = ov * fast_tanh(creg);
            hlast = h;
            hbuf[((t + 1) & 1) * 256 + eb * 128 + eu] = h;
            g_h[((size_t)t * BATCH + b0 + eb) * HDIM + eu] = h;
        }
        __syncthreads();
    }

    if (write_state) {
        state_out[(b0 + eb) * HDIM + eu] = hlast;
        state_out[BATCH * HDIM + (b0 + eb) * HDIM + eu] = creg;
    }
}

/* ------------------------------------------------------------------ */
/* Kernel 3: out = h_all @ fc_W^T + fc_b.                             */
/* ------------------------------------------------------------------ */
__global__ __launch_bounds__(256) void k_fc(
    const float* __restrict__ fcW, const float* __restrict__ fcb,
    float* __restrict__ out)
{
    __shared__ float Ws[NCLS * HDIM];
    __shared__ float bsh[NCLS];
    const int tid = threadIdx.x;
    for (int i = tid; i < NCLS * HDIM; i += 256) Ws[i] = fcW[i];
    if (tid < NCLS) bsh[tid] = fcb[tid];
    __syncthreads();

    const size_t m = (size_t)blockIdx.x * 256 + tid;
    const ulonglong2* hv = (const ulonglong2*)(g_h + m * HDIM);

    ull acc[NCLS];
#pragma unroll
    for (int c = 0; c < NCLS; c++) acc[c] = 0ull;

#pragma unroll 2
    for (int q = 0; q < 32; q++) {
        ulonglong2 h = hv[q];
#pragma unroll
        for (int c = 0; c < NCLS; c++) {
            ulonglong2 w = *(const ulonglong2*)&Ws[c * HDIM + 4 * q];
            ffma2(acc[c], w.x, h.x);
            ffma2(acc[c], w.y, h.y);
        }
    }
    float* po = out + m * NCLS;
#pragma unroll
    for (int c = 0; c < NCLS; c++) po[c] = bsh[c] + hsum2(acc[c]);
}

/* ------------------------------------------------------------------ */
extern "C" void kernel_launch(void* const* d_in, const int* in_sizes, int n_in,
                              void* d_out, int out_size)
{
    const float* X   = (const float*)d_in[0];
    const float* hid = (const float*)d_in[1];
    const float* cel = (const float*)d_in[2];
    const float* Wih = (const float*)d_in[3];
    const float* Whh = (const float*)d_in[4];
    const float* bih = (const float*)d_in[5];
    const float* bhh = (const float*)d_in[6];
    const float* fcW = (const float*)d_in[7];
    const float* fcb = (const float*)d_in[8];
    float* out = (float*)d_out;

    const int smem2 = (512 * 36 + 512 + 1024) * 4;            /* 79872 */
    cudaFuncSetAttribute(k1_mma, cudaFuncAttributeMaxDynamicSharedMemorySize, K1_SMEM);
    cudaFuncSetAttribute(k_lstm, cudaFuncAttributeMaxDynamicSharedMemorySize, smem2);

    k0_split<<<(X_F4 + W_F4) / 256, 256>>>(X, Wih);
    k1_mma<<<dim3(G4 / 64, M_TOT / 128), 256, K1_SMEM>>>(bih, bhh);

    const int main_elems = T_STEPS * BATCH * NCLS;
    int wstate = (out_size >= main_elems + 2 * BATCH * HDIM) ? 1 : 0;
    float* state_out = out + (size_t)main_elems;
    k_lstm<<<BATCH / 2, 256, smem2>>>(hid, cel, Whh, state_out, wstate);

    k_fc<<<M_TOT / 256, 256>>>(fcW, fcb, out);
}